// round 2
// baseline (speedup 1.0000x reference)
#include <cuda_runtime.h>

// Lattice LRU recurrence, fp32 baseline.
// Single persistent kernel, grid = 128 CTAs (all co-resident), custom
// wrap-safe grid barrier. Per cell: stage1 = big gate GEMM (128x2048,K=1024),
// stage2 = two candidate GEMMs (each 128x512,K=1024) + state update.
// Stage-1 epilogue also precomputes the elementwise products h1*r / h0*q so
// every stage-2 A-operand is a plain strided load.

#define H_    512
#define B_    128
#define T_    512
#define L_    4
#define J_    2
#define K2H   1024
#define N4H   2048
#define NBLK  128
#define NTHR  256
#define KC    32
#define NCHUNK (K2H / KC)

// ---- device scratch (no allocation allowed) ----
__device__ __align__(128) float d_g[B_ * N4H];        // sigmoid gates (z0,z1,r,q)
__device__ __align__(128) float d_ar[B_ * H_];        // h1 * r
__device__ __align__(128) float d_aq[B_ * H_];        // h0 * q
__device__ __align__(128) float d_h0buf[2][B_ * H_];  // ping-pong h0
__device__ __align__(128) float d_h1buf[2][B_ * H_];  // ping-pong h1
__device__ __align__(128) float d_H1[L_ * B_ * H_];   // persistent per-layer state
__device__ unsigned int g_bar = 0;

__device__ __forceinline__ void grid_barrier() {
    __syncthreads();
    if (threadIdx.x == 0) {
        __threadfence();
        unsigned ticket = atomicAdd(&g_bar, 1u);
        // NBLK = 128 divides 2^32 -> wrap-safe phase arithmetic
        unsigned target = (ticket & ~(unsigned)(NBLK - 1)) + NBLK;
        while ((int)(*(volatile unsigned*)&g_bar - target) < 0) {
            __nanosleep(32);
        }
        __threadfence();
    }
    __syncthreads();
}

// Tiled GEMM: C[128 x (8*CT)] tile, K = 1024.
// A assembled from two strided sources: a0 for k in [0,512), a1 for [512,1024).
// Thread (rowg = tid>>3, colg = tid&7) computes rows rowg*4..+3, cols colg*CT..+CT-1.
template <int CT>
__device__ __forceinline__ void gemm_tile(
    const float* __restrict__ a0, int lda0,
    const float* __restrict__ a1, int lda1,
    const float* __restrict__ W, int ldw,
    float* acc,
    float (*As)[KC + 4], float (*Bs)[20])
{
    const int tid  = threadIdx.x;
    const int rowg = tid >> 3;
    const int colg = tid & 7;

#pragma unroll
    for (int i = 0; i < 4 * CT; ++i) acc[i] = 0.f;

    const int  nb_f4 = 2 * CT;                 // float4s per k-row of B tile
    const bool bload = (tid < KC * nb_f4);
    const int  bk    = bload ? tid / nb_f4 : 0;
    const int  bc4   = bload ? tid % nb_f4 : 0;

    float4 av[4];
    float4 bv = make_float4(0.f, 0.f, 0.f, 0.f);

    // prologue: stage chunk 0 into registers
    {
#pragma unroll
        for (int i = 0; i < 4; ++i) {
            int idx = tid + i * NTHR;          // 0..1023
            int b = idx >> 3, f4 = idx & 7;
            av[i] = __ldcg((const float4*)(a0 + (size_t)b * lda0 + f4 * 4));
        }
        if (bload) bv = *(const float4*)(W + (size_t)bk * ldw + bc4 * 4);
    }

    for (int kc = 0; kc < NCHUNK; ++kc) {
        __syncthreads();                       // previous compute finished
#pragma unroll
        for (int i = 0; i < 4; ++i) {
            int idx = tid + i * NTHR;
            int b = idx >> 3, f4 = idx & 7;
            *(float4*)&As[b][f4 * 4] = av[i];
        }
        if (bload) *(float4*)&Bs[bk][bc4 * 4] = bv;
        __syncthreads();

        // prefetch next chunk (overlaps with compute below)
        if (kc + 1 < NCHUNK) {
            int kbase = (kc + 1) * KC;
            const float* asrc = (kbase < H_) ? a0 : a1;
            int lda  = (kbase < H_) ? lda0 : lda1;
            int koff = (kbase < H_) ? kbase : kbase - H_;
#pragma unroll
            for (int i = 0; i < 4; ++i) {
                int idx = tid + i * NTHR;
                int b = idx >> 3, f4 = idx & 7;
                av[i] = __ldcg((const float4*)(asrc + (size_t)b * lda + koff + f4 * 4));
            }
            if (bload) bv = *(const float4*)(W + (size_t)(kbase + bk) * ldw + bc4 * 4);
        }

#pragma unroll
        for (int kk = 0; kk < KC; ++kk) {
            float a0v = As[rowg * 4 + 0][kk];
            float a1v = As[rowg * 4 + 1][kk];
            float a2v = As[rowg * 4 + 2][kk];
            float a3v = As[rowg * 4 + 3][kk];
#pragma unroll
            for (int c = 0; c < CT; ++c) {
                float bb = Bs[kk][colg * CT + c];
                acc[0 * CT + c] = fmaf(a0v, bb, acc[0 * CT + c]);
                acc[1 * CT + c] = fmaf(a1v, bb, acc[1 * CT + c]);
                acc[2 * CT + c] = fmaf(a2v, bb, acc[2 * CT + c]);
                acc[3 * CT + c] = fmaf(a3v, bb, acc[3 * CT + c]);
            }
        }
    }
}

__global__ void __launch_bounds__(NTHR, 1) lattice_kernel(
    const float* __restrict__ H0in,
    const float* __restrict__ lin_w, const float* __restrict__ lin_b,
    const float* __restrict__ g0w,  const float* __restrict__ g0b,
    const float* __restrict__ g1w,  const float* __restrict__ g1b,
    float* __restrict__ out)
{
    __shared__ float As[B_][KC + 4];   // [128][36]
    __shared__ float Bs[KC][20];

    const int tid  = threadIdx.x;
    const int blk  = blockIdx.x;
    const int rowg = tid >> 3;
    const int colg = tid & 7;

    // reset persistent state every launch (graph replays reuse globals)
    for (int i = tid + blk * NTHR; i < L_ * B_ * H_; i += NBLK * NTHR)
        d_H1[i] = 0.f;
    grid_barrier();

    float* out_h1 = out + (size_t)B_ * T_ * H_;

    for (int t = 0; t < T_; ++t) {
        int p = 0;
        for (int l = 0; l < L_; ++l) {
            for (int j = 0; j < J_; ++j) {
                const int  cell  = l * J_ + j;
                const bool first = (l == 0 && j == 0);
                const bool last  = (l == L_ - 1 && j == J_ - 1);

                const float* h0src = first ? (H0in + (size_t)t * H_) : d_h0buf[p];
                const int    lda0  = first ? (T_ * H_) : H_;
                const float* h1src = (j == 0) ? (d_H1 + (size_t)l * B_ * H_) : d_h1buf[p];
                float*       h0dst = last ? (out + (size_t)t * H_) : d_h0buf[p ^ 1];
                const int    ldh0d = last ? (T_ * H_) : H_;
                float*       h1dst = (j == J_ - 1) ? (d_H1 + (size_t)l * B_ * H_)
                                                   : d_h1buf[p ^ 1];

                // ---------- stage 1: G = sigmoid([h0,h1] @ lin_w + lin_b) ----------
                {
                    const float* W = lin_w + (size_t)cell * K2H * N4H + blk * 16;
                    float acc[8];
                    gemm_tile<2>(h0src, lda0, h1src, H_, W, N4H, acc, As, Bs);

                    const int    colbase = blk * 16;
                    const float* bptr = lin_b + (size_t)cell * N4H + colbase;
#pragma unroll
                    for (int r = 0; r < 4; ++r) {
                        int b = rowg * 4 + r;
#pragma unroll
                        for (int c = 0; c < 2; ++c) {
                            int col = colbase + colg * 2 + c;
                            float v = acc[r * 2 + c] + bptr[colg * 2 + c];
                            float s = 1.f / (1.f + expf(-v));
                            d_g[b * N4H + col] = s;
                            if (col >= 2 * H_ && col < 3 * H_) {        // r-gate
                                int cc = col - 2 * H_;
                                d_ar[b * H_ + cc] = s * __ldcg(&h1src[b * H_ + cc]);
                            } else if (col >= 3 * H_) {                 // q-gate
                                int cc = col - 3 * H_;
                                d_aq[b * H_ + cc] =
                                    s * __ldcg(&h0src[(size_t)b * lda0 + cc]);
                            }
                        }
                    }
                }
                grid_barrier();

                // ---------- stage 2: candidates + state update ----------
                {
                    const int cc0 = blk * 8;
                    float acc[4];
                    if (cc0 < H_) {
                        // h0_cap = tanh([h0, h1*r] @ g0w + g0b); h1' = z1*h0_cap+(1-z1)*h1
                        const float* W = g0w + (size_t)cell * K2H * H_ + cc0;
                        gemm_tile<1>(h0src, lda0, d_ar, H_, W, H_, acc, As, Bs);
                        const float* bptr = g0b + (size_t)cell * H_ + cc0;
                        const int n = cc0 + colg;
#pragma unroll
                        for (int r = 0; r < 4; ++r) {
                            int b = rowg * 4 + r;
                            float hc  = tanhf(acc[r] + bptr[colg]);
                            float z1  = __ldcg(&d_g[b * N4H + H_ + n]);
                            float h1o = __ldcg(&h1src[b * H_ + n]);
                            h1dst[b * H_ + n] = z1 * hc + (1.f - z1) * h1o;
                        }
                    } else {
                        // h1_cap = tanh([h1, h0*q] @ g1w + g1b); h0' = z0*h1_cap+(1-z0)*h0
                        const int n0 = cc0 - H_;
                        const float* W = g1w + (size_t)cell * K2H * H_ + n0;
                        gemm_tile<1>(h1src, H_, d_aq, H_, W, H_, acc, As, Bs);
                        const float* bptr = g1b + (size_t)cell * H_ + n0;
                        const int n = n0 + colg;
#pragma unroll
                        for (int r = 0; r < 4; ++r) {
                            int b = rowg * 4 + r;
                            float hc  = tanhf(acc[r] + bptr[colg]);
                            float z0  = __ldcg(&d_g[b * N4H + n]);
                            float h0o = __ldcg(&h0src[(size_t)b * lda0 + n]);
                            h0dst[(size_t)b * ldh0d + n] = z0 * hc + (1.f - z0) * h0o;
                        }
                    }
                }
                grid_barrier();
                p ^= 1;
            }
        }
    }

    // H1_final: out2[b, l, h] = d_H1[l, b, h]
    for (int i = tid + blk * NTHR; i < L_ * B_ * H_; i += NBLK * NTHR) {
        int h    = i & (H_ - 1);
        int rest = i >> 9;          // l*B + b
        int b    = rest & (B_ - 1);
        int l    = rest >> 7;
        out_h1[((size_t)b * L_ + l) * H_ + h] = __ldcg(&d_H1[i]);
    }
}

extern "C" void kernel_launch(void* const* d_in, const int* in_sizes, int n_in,
                              void* d_out, int out_size)
{
    const float* H0in  = (const float*)d_in[0];
    const float* lin_w = (const float*)d_in[1];
    const float* lin_b = (const float*)d_in[2];
    const float* g0w   = (const float*)d_in[3];
    const float* g0b   = (const float*)d_in[4];
    const float* g1w   = (const float*)d_in[5];
    const float* g1b   = (const float*)d_in[6];

    lattice_kernel<<<NBLK, NTHR>>>(H0in, lin_w, lin_b, g0w, g0b, g1w, g1b,
                                   (float*)d_out);
}

// round 4
// speedup vs baseline: 1.7137x; 1.7137x over previous
#include <cuda_runtime.h>
#include <cuda_bf16.h>
#include <cstdint>

#define H_    512
#define B_    128
#define T_    512
#define L_    4
#define J_    2
#define NBLK  128
#define NTHR  256
#define KCH   64
#define NCHUNK 16
#define SA_STR 72     // padded bf16 row stride (144B = 9*16B -> conflict-free ldmatrix)
#define SW_STR 72

// ---- converted weights (bf16 hi/lo, transposed to [n][k]) ----
__device__ __nv_bfloat16 d_linw_h[8u * 2048u * 1024u];
__device__ __nv_bfloat16 d_linw_l[8u * 2048u * 1024u];
__device__ __nv_bfloat16 d_gw_h[8u * 1024u * 1024u];   // n<512: g0w, n>=512: g1w
__device__ __nv_bfloat16 d_gw_l[8u * 1024u * 1024u];

// ---- fp32 scratch ----
__device__ __align__(128) float d_z[B_ * 1024];        // z0 | z1
__device__ __align__(128) float d_ar[B_ * H_];         // h1 * r
__device__ __align__(128) float d_aq[B_ * H_];         // h0 * q
__device__ __align__(128) float d_h0buf[2][B_ * H_];
__device__ __align__(128) float d_h1buf[2][B_ * H_];
__device__ __align__(128) float d_H1[L_ * B_ * H_];
__device__ unsigned int g_bar = 0;

// ================= helpers =================
__device__ __forceinline__ uint32_t smem_u32(const void* p) {
    uint32_t a;
    asm("{ .reg .u64 t; cvta.to.shared.u64 t, %1; cvt.u32.u64 %0, t; }"
        : "=r"(a) : "l"(p));
    return a;
}
__device__ __forceinline__ void ldm_x4(uint32_t* r, uint32_t addr) {
    asm volatile("ldmatrix.sync.aligned.m8n8.x4.shared.b16 {%0,%1,%2,%3}, [%4];"
                 : "=r"(r[0]), "=r"(r[1]), "=r"(r[2]), "=r"(r[3]) : "r"(addr));
}
__device__ __forceinline__ void ldm_x2(uint32_t* r, uint32_t addr) {
    asm volatile("ldmatrix.sync.aligned.m8n8.x2.shared.b16 {%0,%1}, [%2];"
                 : "=r"(r[0]), "=r"(r[1]) : "r"(addr));
}
__device__ __forceinline__ void mma16816(float* c, const uint32_t* a, const uint32_t* b) {
    asm volatile(
        "mma.sync.aligned.m16n8k16.row.col.f32.bf16.bf16.f32 "
        "{%0,%1,%2,%3}, {%4,%5,%6,%7}, {%8,%9}, {%0,%1,%2,%3};"
        : "+f"(c[0]), "+f"(c[1]), "+f"(c[2]), "+f"(c[3])
        : "r"(a[0]), "r"(a[1]), "r"(a[2]), "r"(a[3]), "r"(b[0]), "r"(b[1]));
}
__device__ __forceinline__ void split2(float x, unsigned short& h, unsigned short& l) {
    __nv_bfloat16 hb = __float2bfloat16(x);
    float r = x - __bfloat162float(hb);
    __nv_bfloat16 lb = __float2bfloat16(r);
    h = *reinterpret_cast<unsigned short*>(&hb);
    l = *reinterpret_cast<unsigned short*>(&lb);
}
__device__ __forceinline__ void grid_barrier() {
    __syncthreads();
    if (threadIdx.x == 0) {
        __threadfence();
        unsigned ticket = atomicAdd(&g_bar, 1u);
        unsigned target = (ticket & ~(unsigned)(NBLK - 1)) + NBLK;
        while ((int)(*(volatile unsigned*)&g_bar - target) < 0) { __nanosleep(20); }
        __threadfence();
    }
    __syncthreads();
}

// ============ weight pre-conversion: fp32 [k][n] -> bf16 hi/lo [n][k] ============
__global__ void convert_weights(const float* __restrict__ lin_w,
                                const float* __restrict__ g0w,
                                const float* __restrict__ g1w) {
    int t = blockIdx.x * blockDim.x + threadIdx.x;
    const float* src;
    int stride;
    __nv_bfloat16 *dh, *dl;
    if (t < 8 * 2048) {
        int cell = t >> 11, n = t & 2047;
        src = lin_w + (size_t)cell * 1024 * 2048 + n;
        stride = 2048;
        dh = d_linw_h + (size_t)t * 1024;
        dl = d_linw_l + (size_t)t * 1024;
    } else {
        int t2 = t - 8 * 2048;
        if (t2 >= 8 * 1024) return;
        int cell = t2 >> 10, n = t2 & 1023;
        src = (n < 512) ? (g0w + (size_t)cell * 1024 * 512 + n)
                        : (g1w + (size_t)cell * 1024 * 512 + (n - 512));
        stride = 512;
        dh = d_gw_h + (size_t)t2 * 1024;
        dl = d_gw_l + (size_t)t2 * 1024;
    }
    for (int k0 = 0; k0 < 1024; k0 += 8) {
        unsigned short hb[8], lb[8];
#pragma unroll
        for (int i = 0; i < 8; ++i)
            split2(src[(size_t)(k0 + i) * stride], hb[i], lb[i]);
        *(uint4*)(dh + k0) = *(uint4*)hb;
        *(uint4*)(dl + k0) = *(uint4*)lb;
    }
}

// ============ GEMM: C[128 x NT*8] = [src0|src1](128x1024) @ W(NT*8 x 1024)^T ====
// 3-pass bf16 hi/lo (Ah*Wh + Al*Wh + Ah*Wl), fp32 HMMA accumulate in registers.
template <int NT>
__device__ __forceinline__ void run_gemm(
    __nv_bfloat16 (*sAh)[SA_STR], __nv_bfloat16 (*sAl)[SA_STR],
    __nv_bfloat16 (*sWh)[SW_STR], __nv_bfloat16 (*sWl)[SW_STR],
    const float* __restrict__ src0, int lda0,
    const float* __restrict__ src1,
    const __nv_bfloat16* __restrict__ wh,
    const __nv_bfloat16* __restrict__ wl,
    float* acc)
{
    const int tid  = threadIdx.x;
    const int lane = tid & 31;
    const int wid  = tid >> 5;

#pragma unroll
    for (int i = 0; i < NT * 4; ++i) acc[i] = 0.f;

    // ldmatrix lane addresses
    const uint32_t aH = smem_u32(&sAh[wid * 16 + (lane & 15)][(lane >> 4) * 8]);
    const uint32_t aL = smem_u32(&sAl[wid * 16 + (lane & 15)][(lane >> 4) * 8]);
    const int wrow = (lane & 7) + ((lane >> 4) & 1) * 8;
    const int wcol = ((lane >> 3) & 1) * 8;
    const uint32_t wH = smem_u32(&sWh[wrow][wcol]);
    const uint32_t wL = smem_u32(&sWl[wrow][wcol]);

    float4 av[8];
    uint4  wvh, wvl;
    const bool wload = tid < NT * 64;
    const int  wr = tid >> 3, wk = (tid & 7) * 8;

    // prologue: chunk 0 (kbase=0 -> always src0)
    {
#pragma unroll
        for (int it = 0; it < 8; ++it) {
            int i = tid + it * NTHR;
            int m = i >> 4, k = (i & 15) * 4;
            av[it] = __ldcg((const float4*)(src0 + (size_t)m * lda0 + k));
        }
        if (wload) {
            wvh = *(const uint4*)(wh + (size_t)wr * 1024 + wk);
            wvl = *(const uint4*)(wl + (size_t)wr * 1024 + wk);
        }
    }

    for (int kc = 0; kc < NCHUNK; ++kc) {
        __syncthreads();
        // store staged chunk (fp32 -> bf16 hi/lo split for A)
#pragma unroll
        for (int it = 0; it < 8; ++it) {
            int i = tid + it * NTHR;
            int m = i >> 4, k = (i & 15) * 4;
            unsigned short hx, lx, hy, ly, hz, lz, hw2, lw2;
            split2(av[it].x, hx, lx); split2(av[it].y, hy, ly);
            split2(av[it].z, hz, lz); split2(av[it].w, hw2, lw2);
            *(uint2*)&sAh[m][k] =
                make_uint2((uint32_t)hx | ((uint32_t)hy << 16),
                           (uint32_t)hz | ((uint32_t)hw2 << 16));
            *(uint2*)&sAl[m][k] =
                make_uint2((uint32_t)lx | ((uint32_t)ly << 16),
                           (uint32_t)lz | ((uint32_t)lw2 << 16));
        }
        if (wload) { *(uint4*)&sWh[wr][wk] = wvh; *(uint4*)&sWl[wr][wk] = wvl; }
        __syncthreads();

        // prefetch next chunk (overlaps with MMA below)
        if (kc + 1 < NCHUNK) {
            int kb = (kc + 1) * KCH;
            const float* asrc = (kb < H_) ? src0 : src1;
            int lda  = (kb < H_) ? lda0 : H_;
            int koff = (kb < H_) ? kb : kb - H_;
#pragma unroll
            for (int it = 0; it < 8; ++it) {
                int i = tid + it * NTHR;
                int m = i >> 4, k = (i & 15) * 4;
                av[it] = __ldcg((const float4*)(asrc + (size_t)m * lda + koff + k));
            }
            if (wload) {
                wvh = *(const uint4*)(wh + (size_t)wr * 1024 + kb + wk);
                wvl = *(const uint4*)(wl + (size_t)wr * 1024 + kb + wk);
            }
        }

        // compute: 4 k-steps of 16
#pragma unroll
        for (int ks = 0; ks < 4; ++ks) {
            uint32_t ah[4], al[4], bh[4], bl[4];
            ldm_x4(ah, aH + ks * 32);
            ldm_x4(al, aL + ks * 32);
            if (NT == 2) { ldm_x4(bh, wH + ks * 32); ldm_x4(bl, wL + ks * 32); }
            else         { ldm_x2(bh, wH + ks * 32); ldm_x2(bl, wL + ks * 32); }
            mma16816(acc, ah, bh);
            if (NT == 2) mma16816(acc + 4, ah, bh + 2);
            mma16816(acc, al, bh);
            if (NT == 2) mma16816(acc + 4, al, bh + 2);
            mma16816(acc, ah, bl);
            if (NT == 2) mma16816(acc + 4, ah, bl + 2);
        }
    }
}

// =================== main persistent kernel ===================
__global__ void __launch_bounds__(NTHR, 1) lattice_mma(
    const float* __restrict__ H0in,
    const float* __restrict__ lin_b,
    const float* __restrict__ g0b, const float* __restrict__ g1b,
    float* __restrict__ out)
{
    __shared__ __align__(16) __nv_bfloat16 sAh[B_][SA_STR];
    __shared__ __align__(16) __nv_bfloat16 sAl[B_][SA_STR];
    __shared__ __align__(16) __nv_bfloat16 sWh[16][SW_STR];
    __shared__ __align__(16) __nv_bfloat16 sWl[16][SW_STR];

    const int tid  = threadIdx.x;
    const int blk  = blockIdx.x;
    const int lane = tid & 31;
    const int wid  = tid >> 5;
    const int g    = lane >> 2;
    const int tg   = lane & 3;
    const int r0   = wid * 16 + g;
    const int r1   = r0 + 8;

    for (int i = tid + blk * NTHR; i < L_ * B_ * H_; i += NBLK * NTHR)
        d_H1[i] = 0.f;
    grid_barrier();

    float* out_h1 = out + (size_t)B_ * T_ * H_;

    for (int t = 0; t < T_; ++t) {
        int p = 0;
        for (int l = 0; l < L_; ++l) {
            for (int j = 0; j < J_; ++j) {
                const int  cell  = l * J_ + j;
                const bool first = (l == 0 && j == 0);
                const bool last  = (l == L_ - 1 && j == J_ - 1);

                const float* h0src = first ? (H0in + (size_t)t * H_) : d_h0buf[p];
                const int    lda0  = first ? (T_ * H_) : H_;
                const float* h1src = (j == 0) ? (d_H1 + (size_t)l * B_ * H_) : d_h1buf[p];
                float*       h0dst = last ? (out + (size_t)t * H_) : d_h0buf[p ^ 1];
                const int    ldh0d = last ? (T_ * H_) : H_;
                float*       h1dst = (j == J_ - 1) ? (d_H1 + (size_t)l * B_ * H_)
                                                   : d_h1buf[p ^ 1];

                // ---------- stage 1: gates (cols blk*16..+15 of 2048) ----------
                {
                    const __nv_bfloat16* wh =
                        d_linw_h + ((size_t)cell * 2048 + blk * 16) * 1024;
                    const __nv_bfloat16* wl =
                        d_linw_l + ((size_t)cell * 2048 + blk * 16) * 1024;
                    float acc[8];
                    run_gemm<2>(sAh, sAl, sWh, sWl, h0src, lda0, h1src, wh, wl, acc);

                    const int    colbase = blk * 16;
                    const int    region  = blk >> 5;       // 0:z0 1:z1 2:r 3:q
                    const float* bp = lin_b + (size_t)cell * 2048 + colbase;
#pragma unroll
                    for (int nt = 0; nt < 2; ++nt) {
                        const int   cl  = nt * 8 + tg * 2;
                        const int   col = colbase + cl;
                        const float b0  = bp[cl], b1 = bp[cl + 1];
#pragma unroll
                        for (int rr = 0; rr < 2; ++rr) {
                            const int   m  = rr ? r1 : r0;
                            const float v0 = acc[nt * 4 + rr * 2 + 0] + b0;
                            const float v1 = acc[nt * 4 + rr * 2 + 1] + b1;
                            const float s0 = 1.f / (1.f + __expf(-v0));
                            const float s1 = 1.f / (1.f + __expf(-v1));
                            if (region < 2) {
                                *(float2*)&d_z[m * 1024 + col] = make_float2(s0, s1);
                            } else if (region == 2) {
                                const int cc = col - 2 * H_;
                                float2 h = *(const float2*)__builtin_assume_aligned(
                                    &h1src[m * H_ + cc], 8);
                                float2 hv = make_float2(__ldcg(&h1src[m * H_ + cc]),
                                                        __ldcg(&h1src[m * H_ + cc + 1]));
                                (void)h;
                                *(float2*)&d_ar[m * H_ + cc] =
                                    make_float2(s0 * hv.x, s1 * hv.y);
                            } else {
                                const int cc = col - 3 * H_;
                                float2 hv = make_float2(
                                    __ldcg(&h0src[(size_t)m * lda0 + cc]),
                                    __ldcg(&h0src[(size_t)m * lda0 + cc + 1]));
                                *(float2*)&d_aq[m * H_ + cc] =
                                    make_float2(s0 * hv.x, s1 * hv.y);
                            }
                        }
                    }
                }
                grid_barrier();

                // ---------- stage 2: candidates + state update ----------
                {
                    const bool g0side = (blk < 64);
                    const float* s0 = g0side ? h0src : h1src;
                    const int    sl = g0side ? lda0 : H_;
                    const float* s1 = g0side ? d_ar : d_aq;
                    const __nv_bfloat16* wh =
                        d_gw_h + ((size_t)cell * 1024 + blk * 8) * 1024;
                    const __nv_bfloat16* wl =
                        d_gw_l + ((size_t)cell * 1024 + blk * 8) * 1024;
                    float acc[4];
                    run_gemm<1>(sAh, sAl, sWh, sWl, s0, sl, s1, wh, wl, acc);

                    const int n0  = g0side ? blk * 8 : (blk - 64) * 8;
                    const int col = n0 + tg * 2;
                    if (g0side) {
                        const float* bp = g0b + (size_t)cell * H_ + col;
                        const float  b0 = bp[0], b1 = bp[1];
#pragma unroll
                        for (int rr = 0; rr < 2; ++rr) {
                            const int   m  = rr ? r1 : r0;
                            const float c0 = tanhf(acc[rr * 2 + 0] + b0);
                            const float c1 = tanhf(acc[rr * 2 + 1] + b1);
                            const float z0v = __ldcg(&d_z[m * 1024 + H_ + col]);
                            const float z1v = __ldcg(&d_z[m * 1024 + H_ + col + 1]);
                            const float o0 = __ldcg(&h1src[m * H_ + col]);
                            const float o1 = __ldcg(&h1src[m * H_ + col + 1]);
                            *(float2*)&h1dst[m * H_ + col] =
                                make_float2(z0v * c0 + (1.f - z0v) * o0,
                                            z1v * c1 + (1.f - z1v) * o1);
                        }
                    } else {
                        const float* bp = g1b + (size_t)cell * H_ + col;
                        const float  b0 = bp[0], b1 = bp[1];
#pragma unroll
                        for (int rr = 0; rr < 2; ++rr) {
                            const int   m  = rr ? r1 : r0;
                            const float c0 = tanhf(acc[rr * 2 + 0] + b0);
                            const float c1 = tanhf(acc[rr * 2 + 1] + b1);
                            const float z0v = __ldcg(&d_z[m * 1024 + col]);
                            const float z1v = __ldcg(&d_z[m * 1024 + col + 1]);
                            const float o0 = __ldcg(&h0src[(size_t)m * lda0 + col]);
                            const float o1 = __ldcg(&h0src[(size_t)m * lda0 + col + 1]);
                            *(float2*)&h0dst[(size_t)m * ldh0d + col] =
                                make_float2(z0v * c0 + (1.f - z0v) * o0,
                                            z1v * c1 + (1.f - z1v) * o1);
                        }
                    }
                }
                grid_barrier();
                p ^= 1;
            }
        }
    }

    // H1_final: out2[b, l, h] = d_H1[l, b, h]
    for (int i = tid + blk * NTHR; i < L_ * B_ * H_; i += NBLK * NTHR) {
        int h    = i & (H_ - 1);
        int rest = i >> 9;
        int b    = rest & (B_ - 1);
        int l    = rest >> 7;
        out_h1[((size_t)b * L_ + l) * H_ + h] = __ldcg(&d_H1[i]);
    }
}

extern "C" void kernel_launch(void* const* d_in, const int* in_sizes, int n_in,
                              void* d_out, int out_size)
{
    const float* H0in  = (const float*)d_in[0];
    const float* lin_w = (const float*)d_in[1];
    const float* lin_b = (const float*)d_in[2];
    const float* g0w   = (const float*)d_in[3];
    const float* g0b   = (const float*)d_in[4];
    const float* g1w   = (const float*)d_in[5];
    const float* g1b   = (const float*)d_in[6];

    convert_weights<<<96, 256>>>(lin_w, g0w, g1w);
    lattice_mma<<<NBLK, NTHR>>>(H0in, lin_b, g0b, g1b, (float*)d_out);
}

// round 5
// speedup vs baseline: 1.9266x; 1.1243x over previous
#include <cuda_runtime.h>
#include <cuda_bf16.h>
#include <cstdint>

#define H_    512
#define B_    128
#define T_    512
#define L_    4
#define J_    2
#define NBLK  128
#define NTHR  256
#define KCH   64
#define NCHUNK 16
#define NSTG  4

// smem stage layout (bytes): Ah[128][72]b16 | Al | Wh[16][72] | Wl
#define ROWB   144
#define OFF_AL 18432
#define OFF_WH 36864
#define OFF_WL 39168
#define STG_SZ 41472
#define SMEM_TOTAL (NSTG * STG_SZ)   // 165888

// ---- converted weights (bf16 hi/lo, transposed to [n][k]) ----
__device__ __nv_bfloat16 d_linw_h[8u * 2048u * 1024u];
__device__ __nv_bfloat16 d_linw_l[8u * 2048u * 1024u];
__device__ __nv_bfloat16 d_gw_h[8u * 1024u * 1024u];   // n<512: g0w, n>=512: g1w
__device__ __nv_bfloat16 d_gw_l[8u * 1024u * 1024u];

// ---- fp32 state ----
__device__ __align__(128) float d_z[B_ * 1024];        // z0 | z1
__device__ __align__(128) float d_h0buf[2][B_ * H_];
__device__ __align__(128) float d_h1buf[2][B_ * H_];
__device__ __align__(128) float d_H1[L_ * B_ * H_];
// ---- pre-split bf16 hi/lo GEMM A operands ----
__device__ __align__(128) __nv_bfloat16 d_x0h[B_ * H_], d_x0l[B_ * H_];     // input col
__device__ __align__(128) __nv_bfloat16 d_h0h[2][B_ * H_], d_h0l[2][B_ * H_];
__device__ __align__(128) __nv_bfloat16 d_h1h[2][B_ * H_], d_h1l[2][B_ * H_];
__device__ __align__(128) __nv_bfloat16 d_H1h[L_ * B_ * H_], d_H1l[L_ * B_ * H_];
__device__ __align__(128) __nv_bfloat16 d_arh[B_ * H_], d_arl[B_ * H_];
__device__ __align__(128) __nv_bfloat16 d_aqh[B_ * H_], d_aql[B_ * H_];
__device__ unsigned int g_bar = 0;

// ================= helpers =================
__device__ __forceinline__ uint32_t smem_u32(const void* p) {
    uint32_t a;
    asm("{ .reg .u64 t; cvta.to.shared.u64 t, %1; cvt.u32.u64 %0, t; }"
        : "=r"(a) : "l"(p));
    return a;
}
__device__ __forceinline__ void cpa16(uint32_t d, const void* s) {
    asm volatile("cp.async.cg.shared.global [%0], [%1], 16;" :: "r"(d), "l"(s));
}
__device__ __forceinline__ void cp_commit() {
    asm volatile("cp.async.commit_group;" ::: "memory");
}
template <int N>
__device__ __forceinline__ void cp_wait() {
    asm volatile("cp.async.wait_group %0;" :: "n"(N) : "memory");
}
__device__ __forceinline__ void ldm_x4(uint32_t* r, uint32_t addr) {
    asm volatile("ldmatrix.sync.aligned.m8n8.x4.shared.b16 {%0,%1,%2,%3}, [%4];"
                 : "=r"(r[0]), "=r"(r[1]), "=r"(r[2]), "=r"(r[3]) : "r"(addr));
}
__device__ __forceinline__ void ldm_x2(uint32_t* r, uint32_t addr) {
    asm volatile("ldmatrix.sync.aligned.m8n8.x2.shared.b16 {%0,%1}, [%2];"
                 : "=r"(r[0]), "=r"(r[1]) : "r"(addr));
}
__device__ __forceinline__ void mma16816(float* c, const uint32_t* a, const uint32_t* b) {
    asm volatile(
        "mma.sync.aligned.m16n8k16.row.col.f32.bf16.bf16.f32 "
        "{%0,%1,%2,%3}, {%4,%5,%6,%7}, {%8,%9}, {%0,%1,%2,%3};"
        : "+f"(c[0]), "+f"(c[1]), "+f"(c[2]), "+f"(c[3])
        : "r"(a[0]), "r"(a[1]), "r"(a[2]), "r"(a[3]), "r"(b[0]), "r"(b[1]));
}
__device__ __forceinline__ void split2(float x, unsigned short& h, unsigned short& l) {
    __nv_bfloat16 hb = __float2bfloat16(x);
    float r = x - __bfloat162float(hb);
    __nv_bfloat16 lb = __float2bfloat16(r);
    h = *reinterpret_cast<unsigned short*>(&hb);
    l = *reinterpret_cast<unsigned short*>(&lb);
}
// split two floats -> packed (hi0|hi1), (lo0|lo1)
__device__ __forceinline__ void split_pack(float x, float y, uint32_t& hi, uint32_t& lo) {
    unsigned short hx, lx, hy, ly;
    split2(x, hx, lx); split2(y, hy, ly);
    hi = (uint32_t)hx | ((uint32_t)hy << 16);
    lo = (uint32_t)lx | ((uint32_t)ly << 16);
}
__device__ __forceinline__ void grid_barrier() {
    __syncthreads();
    if (threadIdx.x == 0) {
        __threadfence();
        unsigned ticket = atomicAdd(&g_bar, 1u);
        unsigned target = (ticket & ~(unsigned)(NBLK - 1)) + NBLK;
        while ((int)(*(volatile unsigned*)&g_bar - target) < 0) { __nanosleep(20); }
        __threadfence();
    }
    __syncthreads();
}

// ============ weight pre-conversion: fp32 [k][n] -> bf16 hi/lo [n][k] ============
__global__ void convert_weights(const float* __restrict__ lin_w,
                                const float* __restrict__ g0w,
                                const float* __restrict__ g1w) {
    int t = blockIdx.x * blockDim.x + threadIdx.x;
    const float* src;
    int stride;
    __nv_bfloat16 *dh, *dl;
    if (t < 8 * 2048) {
        int cell = t >> 11, n = t & 2047;
        src = lin_w + (size_t)cell * 1024 * 2048 + n;
        stride = 2048;
        dh = d_linw_h + (size_t)t * 1024;
        dl = d_linw_l + (size_t)t * 1024;
    } else {
        int t2 = t - 8 * 2048;
        if (t2 >= 8 * 1024) return;
        int cell = t2 >> 10, n = t2 & 1023;
        src = (n < 512) ? (g0w + (size_t)cell * 1024 * 512 + n)
                        : (g1w + (size_t)cell * 1024 * 512 + (n - 512));
        stride = 512;
        dh = d_gw_h + (size_t)t2 * 1024;
        dl = d_gw_l + (size_t)t2 * 1024;
    }
    for (int k0 = 0; k0 < 1024; k0 += 8) {
        unsigned short hb[8], lb[8];
#pragma unroll
        for (int i = 0; i < 8; ++i)
            split2(src[(size_t)(k0 + i) * stride], hb[i], lb[i]);
        *(uint4*)(dh + k0) = *(uint4*)hb;
        *(uint4*)(dl + k0) = *(uint4*)lb;
    }
}

// ====== GEMM: C[128 x NT*8] = [a0|a1](128x1024,bf16 hi/lo) @ W(NT*8 x 1024)^T ===
// A operands pre-split in gmem; cp.async 4-stage pipeline; 3-pass HMMA.
template <int NT>
__device__ __forceinline__ void run_gemm(
    uint32_t smb,
    const __nv_bfloat16* __restrict__ a0h, const __nv_bfloat16* __restrict__ a0l,
    const __nv_bfloat16* __restrict__ a1h, const __nv_bfloat16* __restrict__ a1l,
    const __nv_bfloat16* __restrict__ wh,  const __nv_bfloat16* __restrict__ wl,
    float* acc)
{
    const int tid  = threadIdx.x;
    const int lane = tid & 31;
    const int wid  = tid >> 5;

#pragma unroll
    for (int i = 0; i < NT * 4; ++i) acc[i] = 0.f;

    // ldmatrix lane offsets within a stage
    const uint32_t aOff  = (uint32_t)(wid * 16 + (lane & 15)) * ROWB + (lane >> 4) * 16;
    const uint32_t alOff = aOff + OFF_AL;
    const int wrow = (lane & 7) + ((lane >> 4) & 1) * 8;
    const int wcol = ((lane >> 3) & 1) * 16;
    const uint32_t wOffH = OFF_WH + (uint32_t)wrow * ROWB + wcol;
    const uint32_t wOffL = wOffH + (OFF_WL - OFF_WH);

    // cp.async A mapping: row = tid>>1, 4 granules of 16B each half-row
    const int arow = tid >> 1;
    const int agb  = (tid & 1) * 4;

    auto issue = [&](int kc) {
        const __nv_bfloat16* sh = (kc < 8) ? a0h : a1h;
        const __nv_bfloat16* sl = (kc < 8) ? a0l : a1l;
        const int koff = (kc & 7) * KCH;
        const uint32_t st = smb + (uint32_t)(kc & 3) * STG_SZ;
        const __nv_bfloat16* srh = sh + (size_t)arow * H_ + koff + agb * 8;
        const __nv_bfloat16* srl = sl + (size_t)arow * H_ + koff + agb * 8;
        const uint32_t dA = st + (uint32_t)arow * ROWB + agb * 16;
#pragma unroll
        for (int i = 0; i < 4; ++i) {
            cpa16(dA + i * 16, srh + i * 8);
            cpa16(dA + OFF_AL + i * 16, srl + i * 8);
        }
        if (tid < NT * 64) {
            cpa16(st + OFF_WH + (uint32_t)(tid >> 3) * ROWB + (tid & 7) * 16,
                  wh + (size_t)(tid >> 3) * 1024 + kc * KCH + (tid & 7) * 8);
        } else if (tid < NT * 128) {
            const int t2 = tid - NT * 64;
            cpa16(st + OFF_WL + (uint32_t)(t2 >> 3) * ROWB + (t2 & 7) * 16,
                  wl + (size_t)(t2 >> 3) * 1024 + kc * KCH + (t2 & 7) * 8);
        }
        cp_commit();
    };

    issue(0); issue(1); issue(2);

    for (int kc = 0; kc < NCHUNK; ++kc) {
        if (kc <= NCHUNK - 3)      cp_wait<2>();
        else if (kc == NCHUNK - 2) cp_wait<1>();
        else                       cp_wait<0>();
        __syncthreads();
        if (kc + 3 < NCHUNK) issue(kc + 3);

        const uint32_t sbase = smb + (uint32_t)(kc & 3) * STG_SZ;
#pragma unroll
        for (int ks = 0; ks < 4; ++ks) {
            uint32_t ah[4], al[4], bh[4], bl[4];
            ldm_x4(ah, sbase + aOff + ks * 32);
            ldm_x4(al, sbase + alOff + ks * 32);
            if (NT == 2) { ldm_x4(bh, sbase + wOffH + ks * 32);
                           ldm_x4(bl, sbase + wOffL + ks * 32); }
            else         { ldm_x2(bh, sbase + wOffH + ks * 32);
                           ldm_x2(bl, sbase + wOffL + ks * 32); }
            mma16816(acc, ah, bh);
            if (NT == 2) mma16816(acc + 4, ah, bh + 2);
            mma16816(acc, al, bh);
            if (NT == 2) mma16816(acc + 4, al, bh + 2);
            mma16816(acc, ah, bl);
            if (NT == 2) mma16816(acc + 4, ah, bl + 2);
        }
    }
}

// =================== main persistent kernel ===================
__global__ void __launch_bounds__(NTHR, 1) lattice_mma(
    const float* __restrict__ H0in,
    const float* __restrict__ lin_b,
    const float* __restrict__ g0b, const float* __restrict__ g1b,
    float* __restrict__ out)
{
    extern __shared__ __align__(16) char smraw[];
    const uint32_t smb = smem_u32(smraw);

    const int tid  = threadIdx.x;
    const int blk  = blockIdx.x;
    const int lane = tid & 31;
    const int wid  = tid >> 5;
    const int g    = lane >> 2;
    const int tg   = lane & 3;
    const int r0   = wid * 16 + g;
    const int r1   = r0 + 8;

    // init: zero persistent H1 (+splits), convert input column t=0
    for (int i = tid + blk * NTHR; i < L_ * B_ * H_; i += NBLK * NTHR) {
        d_H1[i] = 0.f;
        d_H1h[i] = __float2bfloat16(0.f);
        d_H1l[i] = __float2bfloat16(0.f);
    }
    for (int e = tid + blk * NTHR; e < B_ * H_; e += NBLK * NTHR) {
        int b = e >> 9, h = e & (H_ - 1);
        float v = __ldg(&H0in[(size_t)b * T_ * H_ + h]);
        unsigned short hh, ll;
        split2(v, hh, ll);
        d_x0h[e] = *reinterpret_cast<__nv_bfloat16*>(&hh);
        d_x0l[e] = *reinterpret_cast<__nv_bfloat16*>(&ll);
    }
    grid_barrier();

    float* out_h1 = out + (size_t)B_ * T_ * H_;

    for (int t = 0; t < T_; ++t) {
        int p = 0;
        for (int l = 0; l < L_; ++l) {
            for (int j = 0; j < J_; ++j) {
                const int  cell  = l * J_ + j;
                const bool first = (l == 0 && j == 0);
                const bool last  = (l == L_ - 1 && j == J_ - 1);

                const float* h0src = first ? (H0in + (size_t)t * H_) : d_h0buf[p];
                const int    lda0  = first ? (T_ * H_) : H_;
                const float* h1src = (j == 0) ? (d_H1 + (size_t)l * B_ * H_) : d_h1buf[p];
                float*       h0dst = last ? (out + (size_t)t * H_) : d_h0buf[p ^ 1];
                const int    ldh0d = last ? (T_ * H_) : H_;
                float*       h1dst = (j == J_ - 1) ? (d_H1 + (size_t)l * B_ * H_)
                                                   : d_h1buf[p ^ 1];
                // split-plane sources/dests
                const __nv_bfloat16* h0sh = first ? d_x0h : d_h0h[p];
                const __nv_bfloat16* h0sl = first ? d_x0l : d_h0l[p];
                const __nv_bfloat16* h1sh = (j == 0) ? (d_H1h + (size_t)l * B_ * H_)
                                                     : d_h1h[p];
                const __nv_bfloat16* h1sl = (j == 0) ? (d_H1l + (size_t)l * B_ * H_)
                                                     : d_h1l[p];
                __nv_bfloat16* h1dh = (j == J_ - 1) ? (d_H1h + (size_t)l * B_ * H_)
                                                    : d_h1h[p ^ 1];
                __nv_bfloat16* h1dl = (j == J_ - 1) ? (d_H1l + (size_t)l * B_ * H_)
                                                    : d_h1l[p ^ 1];
                __nv_bfloat16* h0dh = d_h0h[p ^ 1];
                __nv_bfloat16* h0dl = d_h0l[p ^ 1];

                // ---------- stage 1: gates (cols blk*16..+15 of 2048) ----------
                {
                    const __nv_bfloat16* wh =
                        d_linw_h + ((size_t)cell * 2048 + blk * 16) * 1024;
                    const __nv_bfloat16* wl =
                        d_linw_l + ((size_t)cell * 2048 + blk * 16) * 1024;
                    float acc[8];
                    run_gemm<2>(smb, h0sh, h0sl, h1sh, h1sl, wh, wl, acc);

                    const int    colbase = blk * 16;
                    const int    region  = blk >> 5;       // 0,1:z 2:r 3:q
                    const float* bp = lin_b + (size_t)cell * 2048 + colbase;
#pragma unroll
                    for (int nt = 0; nt < 2; ++nt) {
                        const int   cl  = nt * 8 + tg * 2;
                        const int   col = colbase + cl;
                        const float b0  = bp[cl], b1 = bp[cl + 1];
#pragma unroll
                        for (int rr = 0; rr < 2; ++rr) {
                            const int   m  = rr ? r1 : r0;
                            const float s0 =
                                1.f / (1.f + __expf(-(acc[nt * 4 + rr * 2 + 0] + b0)));
                            const float s1 =
                                1.f / (1.f + __expf(-(acc[nt * 4 + rr * 2 + 1] + b1)));
                            if (region < 2) {
                                *(float2*)&d_z[m * 1024 + col] = make_float2(s0, s1);
                            } else if (region == 2) {
                                const int cc = col - 2 * H_;
                                float a0 = s0 * __ldcg(&h1src[m * H_ + cc]);
                                float a1 = s1 * __ldcg(&h1src[m * H_ + cc + 1]);
                                uint32_t hi, lo;
                                split_pack(a0, a1, hi, lo);
                                *(uint32_t*)&d_arh[m * H_ + cc] = hi;
                                *(uint32_t*)&d_arl[m * H_ + cc] = lo;
                            } else {
                                const int cc = col - 3 * H_;
                                float a0 = s0 * __ldcg(&h0src[(size_t)m * lda0 + cc]);
                                float a1 = s1 * __ldcg(&h0src[(size_t)m * lda0 + cc + 1]);
                                uint32_t hi, lo;
                                split_pack(a0, a1, hi, lo);
                                *(uint32_t*)&d_aqh[m * H_ + cc] = hi;
                                *(uint32_t*)&d_aql[m * H_ + cc] = lo;
                            }
                        }
                    }
                }
                grid_barrier();

                // ---------- stage 2: candidates + state update ----------
                {
                    const bool g0side = (blk < 64);
                    const __nv_bfloat16* a0h = g0side ? h0sh : h1sh;
                    const __nv_bfloat16* a0l = g0side ? h0sl : h1sl;
                    const __nv_bfloat16* a1h = g0side ? d_arh : d_aqh;
                    const __nv_bfloat16* a1l = g0side ? d_arl : d_aql;
                    const __nv_bfloat16* wh =
                        d_gw_h + ((size_t)cell * 1024 + blk * 8) * 1024;
                    const __nv_bfloat16* wl =
                        d_gw_l + ((size_t)cell * 1024 + blk * 8) * 1024;
                    float acc[4];
                    run_gemm<1>(smb, a0h, a0l, a1h, a1l, wh, wl, acc);

                    const int n0  = g0side ? blk * 8 : (blk - 64) * 8;
                    const int col = n0 + tg * 2;
                    if (g0side) {
                        const float* bp = g0b + (size_t)cell * H_ + col;
                        const float  b0 = bp[0], b1 = bp[1];
#pragma unroll
                        for (int rr = 0; rr < 2; ++rr) {
                            const int   m  = rr ? r1 : r0;
                            const float c0 = tanhf(acc[rr * 2 + 0] + b0);
                            const float c1 = tanhf(acc[rr * 2 + 1] + b1);
                            const float z0v = __ldcg(&d_z[m * 1024 + H_ + col]);
                            const float z1v = __ldcg(&d_z[m * 1024 + H_ + col + 1]);
                            const float o0 = __ldcg(&h1src[m * H_ + col]);
                            const float o1 = __ldcg(&h1src[m * H_ + col + 1]);
                            const float n0v = z0v * c0 + (1.f - z0v) * o0;
                            const float n1v = z1v * c1 + (1.f - z1v) * o1;
                            *(float2*)&h1dst[m * H_ + col] = make_float2(n0v, n1v);
                            uint32_t hi, lo;
                            split_pack(n0v, n1v, hi, lo);
                            *(uint32_t*)&h1dh[m * H_ + col] = hi;
                            *(uint32_t*)&h1dl[m * H_ + col] = lo;
                        }
                    } else {
                        const float* bp = g1b + (size_t)cell * H_ + col;
                        const float  b0 = bp[0], b1 = bp[1];
#pragma unroll
                        for (int rr = 0; rr < 2; ++rr) {
                            const int   m  = rr ? r1 : r0;
                            const float c0 = tanhf(acc[rr * 2 + 0] + b0);
                            const float c1 = tanhf(acc[rr * 2 + 1] + b1);
                            const float z0v = __ldcg(&d_z[m * 1024 + col]);
                            const float z1v = __ldcg(&d_z[m * 1024 + col + 1]);
                            const float o0 = __ldcg(&h0src[(size_t)m * lda0 + col]);
                            const float o1 = __ldcg(&h0src[(size_t)m * lda0 + col + 1]);
                            const float n0v = z0v * c0 + (1.f - z0v) * o0;
                            const float n1v = z1v * c1 + (1.f - z1v) * o1;
                            *(float2*)&h0dst[(size_t)m * ldh0d + col] =
                                make_float2(n0v, n1v);
                            if (!last) {
                                uint32_t hi, lo;
                                split_pack(n0v, n1v, hi, lo);
                                *(uint32_t*)&h0dh[m * H_ + col] = hi;
                                *(uint32_t*)&h0dl[m * H_ + col] = lo;
                            }
                        }
                    }
                    // prepare next timestep's input split
                    if (last && t + 1 < T_) {
                        for (int e = tid + blk * NTHR; e < B_ * H_; e += NBLK * NTHR) {
                            int b = e >> 9, h = e & (H_ - 1);
                            float v = __ldg(&H0in[((size_t)b * T_ + (t + 1)) * H_ + h]);
                            unsigned short hh, ll;
                            split2(v, hh, ll);
                            d_x0h[e] = *reinterpret_cast<__nv_bfloat16*>(&hh);
                            d_x0l[e] = *reinterpret_cast<__nv_bfloat16*>(&ll);
                        }
                    }
                }
                grid_barrier();
                p ^= 1;
            }
        }
    }

    // H1_final: out2[b, l, h] = d_H1[l, b, h]
    for (int i = tid + blk * NTHR; i < L_ * B_ * H_; i += NBLK * NTHR) {
        int h    = i & (H_ - 1);
        int rest = i >> 9;
        int b    = rest & (B_ - 1);
        int l    = rest >> 7;
        out_h1[((size_t)b * L_ + l) * H_ + h] = __ldcg(&d_H1[i]);
    }
}

extern "C" void kernel_launch(void* const* d_in, const int* in_sizes, int n_in,
                              void* d_out, int out_size)
{
    const float* H0in  = (const float*)d_in[0];
    const float* lin_w = (const float*)d_in[1];
    const float* lin_b = (const float*)d_in[2];
    const float* g0w   = (const float*)d_in[3];
    const float* g0b   = (const float*)d_in[4];
    const float* g1w   = (const float*)d_in[5];
    const float* g1b   = (const float*)d_in[6];

    cudaFuncSetAttribute(lattice_mma,
                         cudaFuncAttributeMaxDynamicSharedMemorySize, SMEM_TOTAL);

    convert_weights<<<96, 256>>>(lin_w, g0w, g1w);
    lattice_mma<<<NBLK, NTHR, SMEM_TOTAL>>>(H0in, lin_b, g0b, g1b, (float*)d_out);
}

// round 6
// speedup vs baseline: 3.2124x; 1.6674x over previous
#include <cuda_runtime.h>
#include <cuda_bf16.h>
#include <cstdint>

#define H_    512
#define B_    128
#define T_    512
#define L_    4
#define J_    2
#define NBLK  128
#define NTHR  512

// ---- stage-1 smem layout (per pipeline stage, bytes) ----
// A: 64 rows x 128k bf16 (hi,lo), row stride 272B; W: 32 rows x 128k (hi,lo)
#define S1_ROWB 272
#define S1_A_LO 17408
#define S1_W_HI 34816
#define S1_W_LO 43520
#define S1_SZ   52224
// ---- stage-2 smem layout: A 32 rows x 256k (two K-halves), W 32 rows x 256k
#define S2_ROWB 528
#define S2_A_LO 16896
#define S2_W_HI 33792
#define S2_W_LO 50688
#define S2_SZ   67584
#define SMEM_TOTAL (3 * S2_SZ)   // 202752

// ---- converted weights (bf16 hi/lo, transposed to [n][k]) ----
__device__ __nv_bfloat16 d_linw_h[8u * 2048u * 1024u];
__device__ __nv_bfloat16 d_linw_l[8u * 2048u * 1024u];
__device__ __nv_bfloat16 d_gw_h[8u * 1024u * 1024u];   // n<512: g0w, n>=512: g1w
__device__ __nv_bfloat16 d_gw_l[8u * 1024u * 1024u];

// ---- fp32 state ----
__device__ __align__(128) float d_z[B_ * 1024];        // z0 | z1
__device__ __align__(128) float d_h0buf[2][B_ * H_];
__device__ __align__(128) float d_h1buf[2][B_ * H_];
__device__ __align__(128) float d_H1[L_ * B_ * H_];
// ---- pre-split bf16 hi/lo GEMM A operands ----
__device__ __align__(128) __nv_bfloat16 d_x0h[B_ * H_], d_x0l[B_ * H_];
__device__ __align__(128) __nv_bfloat16 d_h0h[2][B_ * H_], d_h0l[2][B_ * H_];
__device__ __align__(128) __nv_bfloat16 d_h1h[2][B_ * H_], d_h1l[2][B_ * H_];
__device__ __align__(128) __nv_bfloat16 d_H1h[L_ * B_ * H_], d_H1l[L_ * B_ * H_];
__device__ __align__(128) __nv_bfloat16 d_arh[B_ * H_], d_arl[B_ * H_];
__device__ __align__(128) __nv_bfloat16 d_aqh[B_ * H_], d_aql[B_ * H_];
__device__ unsigned int g_bar = 0;

// ================= helpers =================
__device__ __forceinline__ uint32_t smem_u32(const void* p) {
    uint32_t a;
    asm("{ .reg .u64 t; cvta.to.shared.u64 t, %1; cvt.u32.u64 %0, t; }"
        : "=r"(a) : "l"(p));
    return a;
}
__device__ __forceinline__ void cpa16(uint32_t d, const void* s) {
    asm volatile("cp.async.cg.shared.global [%0], [%1], 16;" :: "r"(d), "l"(s));
}
__device__ __forceinline__ void cp_commit() {
    asm volatile("cp.async.commit_group;" ::: "memory");
}
template <int N>
__device__ __forceinline__ void cp_wait() {
    asm volatile("cp.async.wait_group %0;" :: "n"(N) : "memory");
}
__device__ __forceinline__ void ldm_x4(uint32_t* r, uint32_t addr) {
    asm volatile("ldmatrix.sync.aligned.m8n8.x4.shared.b16 {%0,%1,%2,%3}, [%4];"
                 : "=r"(r[0]), "=r"(r[1]), "=r"(r[2]), "=r"(r[3]) : "r"(addr));
}
__device__ __forceinline__ void ldm_x2(uint32_t* r, uint32_t addr) {
    asm volatile("ldmatrix.sync.aligned.m8n8.x2.shared.b16 {%0,%1}, [%2];"
                 : "=r"(r[0]), "=r"(r[1]) : "r"(addr));
}
__device__ __forceinline__ void mma16816(float* c, const uint32_t* a, const uint32_t* b) {
    asm volatile(
        "mma.sync.aligned.m16n8k16.row.col.f32.bf16.bf16.f32 "
        "{%0,%1,%2,%3}, {%4,%5,%6,%7}, {%8,%9}, {%0,%1,%2,%3};"
        : "+f"(c[0]), "+f"(c[1]), "+f"(c[2]), "+f"(c[3])
        : "r"(a[0]), "r"(a[1]), "r"(a[2]), "r"(a[3]), "r"(b[0]), "r"(b[1]));
}
__device__ __forceinline__ void split2(float x, unsigned short& h, unsigned short& l) {
    __nv_bfloat16 hb = __float2bfloat16(x);
    float r = x - __bfloat162float(hb);
    __nv_bfloat16 lb = __float2bfloat16(r);
    h = *reinterpret_cast<unsigned short*>(&hb);
    l = *reinterpret_cast<unsigned short*>(&lb);
}
__device__ __forceinline__ void split_pack(float x, float y, uint32_t& hi, uint32_t& lo) {
    unsigned short hx, lx, hy, ly;
    split2(x, hx, lx); split2(y, hy, ly);
    hi = (uint32_t)hx | ((uint32_t)hy << 16);
    lo = (uint32_t)lx | ((uint32_t)ly << 16);
}
__device__ __forceinline__ float sigf(float v) { return 1.f / (1.f + __expf(-v)); }
__device__ __forceinline__ void grid_barrier() {
    __syncthreads();
    if (threadIdx.x == 0) {
        __threadfence();
        unsigned ticket = atomicAdd(&g_bar, 1u);
        unsigned target = (ticket & ~(unsigned)(NBLK - 1)) + NBLK;
        while ((int)(*(volatile unsigned*)&g_bar - target) < 0) { __nanosleep(20); }
        __threadfence();
    }
    __syncthreads();
}

// ============ weight pre-conversion: fp32 [k][n] -> bf16 hi/lo [n][k] ============
__global__ void convert_weights(const float* __restrict__ lin_w,
                                const float* __restrict__ g0w,
                                const float* __restrict__ g1w) {
    int t = blockIdx.x * blockDim.x + threadIdx.x;
    const float* src;
    int stride;
    __nv_bfloat16 *dh, *dl;
    if (t < 8 * 2048) {
        int cell = t >> 11, n = t & 2047;
        src = lin_w + (size_t)cell * 1024 * 2048 + n;
        stride = 2048;
        dh = d_linw_h + (size_t)t * 1024;
        dl = d_linw_l + (size_t)t * 1024;
    } else {
        int t2 = t - 8 * 2048;
        if (t2 >= 8 * 1024) return;
        int cell = t2 >> 10, n = t2 & 1023;
        src = (n < 512) ? (g0w + (size_t)cell * 1024 * 512 + n)
                        : (g1w + (size_t)cell * 1024 * 512 + (n - 512));
        stride = 512;
        dh = d_gw_h + (size_t)t2 * 1024;
        dl = d_gw_l + (size_t)t2 * 1024;
    }
    for (int k0 = 0; k0 < 1024; k0 += 8) {
        unsigned short hb[8], lb[8];
#pragma unroll
        for (int i = 0; i < 8; ++i)
            split2(src[(size_t)(k0 + i) * stride], hb[i], lb[i]);
        *(uint4*)(dh + k0) = *(uint4*)hb;
        *(uint4*)(dl + k0) = *(uint4*)lb;
    }
}

// ====== stage-1 GEMM: C[64 x 32] tile of [a0|a1](128x1024) @ W(2048x1024)^T ====
__device__ __forceinline__ void gemm_s1(
    uint32_t smb, int mbase, int nbase,
    const __nv_bfloat16* __restrict__ a0h, const __nv_bfloat16* __restrict__ a0l,
    const __nv_bfloat16* __restrict__ a1h, const __nv_bfloat16* __restrict__ a1l,
    const __nv_bfloat16* __restrict__ wh,  const __nv_bfloat16* __restrict__ wl,
    float* acc)
{
    const int tid = threadIdx.x, lane = tid & 31, wid = tid >> 5;
    acc[0] = acc[1] = acc[2] = acc[3] = 0.f;

    const uint32_t aOffH = (uint32_t)((wid & 3) * 16 + (lane & 15)) * S1_ROWB +
                           (lane >> 4) * 16;
    const uint32_t aOffL = aOffH + S1_A_LO;
    const uint32_t wOffH = S1_W_HI +
                           (uint32_t)((wid >> 2) * 8 + (lane & 7)) * S1_ROWB +
                           ((lane >> 3) & 1) * 16;
    const uint32_t wOffL = wOffH + (S1_W_LO - S1_W_HI);

    const int arow = tid >> 3, agr = (tid & 7) * 2;
    const int wrow = (tid >> 3) & 31, wgr = (tid & 7) * 2;

    auto issue = [&](int kc) {
        const uint32_t st = smb + (uint32_t)(kc % 3) * S1_SZ;
        const __nv_bfloat16* ah = (kc < 4) ? a0h : a1h;
        const __nv_bfloat16* al = (kc < 4) ? a0l : a1l;
        const int koff = (kc & 3) * 128;
        const __nv_bfloat16* srh = ah + (size_t)(mbase + arow) * 512 + koff + agr * 8;
        const __nv_bfloat16* srl = al + (size_t)(mbase + arow) * 512 + koff + agr * 8;
        const uint32_t dA = st + (uint32_t)arow * S1_ROWB + agr * 16;
        cpa16(dA, srh);                 cpa16(dA + 16, srh + 8);
        cpa16(dA + S1_A_LO, srl);       cpa16(dA + S1_A_LO + 16, srl + 8);
        const __nv_bfloat16* wsrc = ((tid < 256) ? wh : wl) +
                                    (size_t)(nbase + wrow) * 1024 + kc * 128 + wgr * 8;
        const uint32_t dW = st + ((tid < 256) ? S1_W_HI : S1_W_LO) +
                            (uint32_t)wrow * S1_ROWB + wgr * 16;
        cpa16(dW, wsrc);  cpa16(dW + 16, wsrc + 8);
        cp_commit();
    };

    issue(0); issue(1);
    for (int kc = 0; kc < 8; ++kc) {
        if (kc == 7) cp_wait<0>(); else cp_wait<1>();
        __syncthreads();
        if (kc + 2 < 8) issue(kc + 2);
        const uint32_t base = smb + (uint32_t)(kc % 3) * S1_SZ;
#pragma unroll
        for (int ks = 0; ks < 8; ++ks) {
            uint32_t ah[4], al[4], bh[2], bl[2];
            ldm_x4(ah, base + aOffH + ks * 32);
            ldm_x4(al, base + aOffL + ks * 32);
            ldm_x2(bh, base + wOffH + ks * 32);
            ldm_x2(bl, base + wOffL + ks * 32);
            mma16816(acc, ah, bh);
            mma16816(acc, al, bh);
            mma16816(acc, ah, bl);
        }
    }
}

// ====== stage-2 GEMM: C[32 x 32] tile, in-CTA split-K (2 halves of 512) ======
__device__ __forceinline__ void gemm_s2(
    uint32_t smb, char* smraw, int mbase, int nbase,
    const __nv_bfloat16* __restrict__ s0h, const __nv_bfloat16* __restrict__ s0l,
    const __nv_bfloat16* __restrict__ s1h, const __nv_bfloat16* __restrict__ s1l,
    const __nv_bfloat16* __restrict__ wh,  const __nv_bfloat16* __restrict__ wl,
    float* acc)
{
    const int tid = threadIdx.x, lane = tid & 31, wid = tid >> 5;
    const int tw = wid & 7, khalf = wid >> 3;
    acc[0] = acc[1] = acc[2] = acc[3] = 0.f;

    const uint32_t aOffH = (uint32_t)((tw & 1) * 16 + (lane & 15)) * S2_ROWB +
                           khalf * 256 + (lane >> 4) * 16;
    const uint32_t aOffL = aOffH + S2_A_LO;
    const uint32_t wOffH = S2_W_HI +
                           (uint32_t)((tw >> 1) * 8 + (lane & 7)) * S2_ROWB +
                           khalf * 256 + ((lane >> 3) & 1) * 16;
    const uint32_t wOffL = wOffH + (S2_W_LO - S2_W_HI);

    const int arow = tid >> 4, agr = (tid & 15) * 2;
    const int wpl  = tid >> 8, wwrow = (tid & 255) >> 3, wgb = (tid & 7) * 4;

    auto issue = [&](int kc) {
        const uint32_t st = smb + (uint32_t)(kc % 3) * S2_SZ;
#pragma unroll
        for (int i = 0; i < 2; ++i) {
            int gidx = agr + i;
            const __nv_bfloat16* ph = (gidx < 16) ? s0h : s1h;
            const __nv_bfloat16* pl = (gidx < 16) ? s0l : s1l;
            int kk = kc * 128 + (gidx & 15) * 8;
            cpa16(st + (uint32_t)arow * S2_ROWB + gidx * 16,
                  ph + (size_t)(mbase + arow) * 512 + kk);
            cpa16(st + S2_A_LO + (uint32_t)arow * S2_ROWB + gidx * 16,
                  pl + (size_t)(mbase + arow) * 512 + kk);
        }
        const __nv_bfloat16* wp = wpl ? wl : wh;
        const uint32_t wdst = st + (wpl ? S2_W_LO : S2_W_HI) +
                              (uint32_t)wwrow * S2_ROWB;
#pragma unroll
        for (int i = 0; i < 4; ++i) {
            int gidx = wgb + i;
            int kk = (gidx < 16) ? (kc * 128 + gidx * 8)
                                 : (512 + kc * 128 + (gidx - 16) * 8);
            cpa16(wdst + gidx * 16, wp + (size_t)(nbase + wwrow) * 1024 + kk);
        }
        cp_commit();
    };

    issue(0); issue(1);
    for (int kc = 0; kc < 4; ++kc) {
        if (kc == 3) cp_wait<0>(); else cp_wait<1>();
        __syncthreads();
        if (kc + 2 < 4) issue(kc + 2);
        const uint32_t base = smb + (uint32_t)(kc % 3) * S2_SZ;
#pragma unroll
        for (int ks = 0; ks < 8; ++ks) {
            uint32_t ah[4], al[4], bh[2], bl[2];
            ldm_x4(ah, base + aOffH + ks * 32);
            ldm_x4(al, base + aOffL + ks * 32);
            ldm_x2(bh, base + wOffH + ks * 32);
            ldm_x2(bl, base + wOffL + ks * 32);
            mma16816(acc, ah, bh);
            mma16816(acc, al, bh);
            mma16816(acc, ah, bl);
        }
    }
    // split-K reduction: half-1 warps stash partials in (now idle) buffer 1
    float* red = (float*)(smraw + S2_SZ);
    if (khalf == 1)
        *(float4*)&red[(size_t)((wid - 8) * 32 + lane) * 4] =
            make_float4(acc[0], acc[1], acc[2], acc[3]);
    __syncthreads();
    if (khalf == 0) {
        float4 o = *(float4*)&red[(size_t)(wid * 32 + lane) * 4];
        acc[0] += o.x; acc[1] += o.y; acc[2] += o.z; acc[3] += o.w;
    }
}

// =================== main persistent kernel ===================
__global__ void __launch_bounds__(NTHR, 1) lattice_mma(
    const float* __restrict__ H0in,
    const float* __restrict__ lin_b,
    const float* __restrict__ g0b, const float* __restrict__ g1b,
    float* __restrict__ out)
{
    extern __shared__ __align__(16) char smraw[];
    const uint32_t smb = smem_u32(smraw);

    const int tid  = threadIdx.x;
    const int blk  = blockIdx.x;
    const int lane = tid & 31;
    const int wid  = tid >> 5;
    const int g    = lane >> 2;
    const int tg   = lane & 3;

    for (int i = tid + blk * NTHR; i < L_ * B_ * H_; i += NBLK * NTHR) {
        d_H1[i] = 0.f;
        d_H1h[i] = __float2bfloat16(0.f);
        d_H1l[i] = __float2bfloat16(0.f);
    }
    for (int e = tid + blk * NTHR; e < B_ * H_; e += NBLK * NTHR) {
        int b = e >> 9, h = e & (H_ - 1);
        float v = __ldg(&H0in[(size_t)b * T_ * H_ + h]);
        unsigned short hh, ll;
        split2(v, hh, ll);
        d_x0h[e] = *reinterpret_cast<__nv_bfloat16*>(&hh);
        d_x0l[e] = *reinterpret_cast<__nv_bfloat16*>(&ll);
    }
    grid_barrier();

    float* out_h1 = out + (size_t)B_ * T_ * H_;

    // tile coords
    const int m1base = (blk & 1) * 64, n1base = (blk >> 1) * 32;
    const int m2base = (blk & 3) * 32, n2base = (blk >> 2) * 32;
    const bool g0side = (n2base < 512);

    for (int t = 0; t < T_; ++t) {
        int p = 0;
        for (int l = 0; l < L_; ++l) {
            for (int j = 0; j < J_; ++j) {
                const int  cell  = l * J_ + j;
                const bool first = (l == 0 && j == 0);
                const bool last  = (l == L_ - 1 && j == J_ - 1);

                const float* h0src = first ? (H0in + (size_t)t * H_) : d_h0buf[p];
                const int    lda0  = first ? (T_ * H_) : H_;
                const float* h1src = (j == 0) ? (d_H1 + (size_t)l * B_ * H_) : d_h1buf[p];
                float*       h0dst = last ? (out + (size_t)t * H_) : d_h0buf[p ^ 1];
                const int    ldh0d = last ? (T_ * H_) : H_;
                float*       h1dst = (j == J_ - 1) ? (d_H1 + (size_t)l * B_ * H_)
                                                   : d_h1buf[p ^ 1];
                const __nv_bfloat16* h0sh = first ? d_x0h : d_h0h[p];
                const __nv_bfloat16* h0sl = first ? d_x0l : d_h0l[p];
                const __nv_bfloat16* h1sh = (j == 0) ? (d_H1h + (size_t)l * B_ * H_)
                                                     : d_h1h[p];
                const __nv_bfloat16* h1sl = (j == 0) ? (d_H1l + (size_t)l * B_ * H_)
                                                     : d_h1l[p];
                __nv_bfloat16* h1dh = (j == J_ - 1) ? (d_H1h + (size_t)l * B_ * H_)
                                                    : d_h1h[p ^ 1];
                __nv_bfloat16* h1dl = (j == J_ - 1) ? (d_H1l + (size_t)l * B_ * H_)
                                                    : d_h1l[p ^ 1];
                __nv_bfloat16* h0dh = d_h0h[p ^ 1];
                __nv_bfloat16* h0dl = d_h0l[p ^ 1];

                // ---------- stage 1: gate GEMM (64x32 tile) ----------
                {
                    float acc[4];
                    gemm_s1(smb, m1base, n1base,
                            h0sh, h0sl, h1sh, h1sl,
                            d_linw_h + (size_t)cell * 2048 * 1024,
                            d_linw_l + (size_t)cell * 2048 * 1024, acc);

                    const int m0 = m1base + (wid & 3) * 16 + g, m1r = m0 + 8;
                    const int col = n1base + (wid >> 2) * 8 + tg * 2;
                    const float* bp = lin_b + (size_t)cell * 2048;
                    const float b0 = bp[col], b1 = bp[col + 1];
                    const float s00 = sigf(acc[0] + b0), s01 = sigf(acc[1] + b1);
                    const float s10 = sigf(acc[2] + b0), s11 = sigf(acc[3] + b1);
                    if (col < 1024) {
                        *(float2*)&d_z[m0 * 1024 + col] = make_float2(s00, s01);
                        *(float2*)&d_z[m1r * 1024 + col] = make_float2(s10, s11);
                    } else if (col < 1536) {
                        const int cc = col - 1024;
                        uint32_t hi, lo;
                        split_pack(s00 * __ldcg(&h1src[m0 * H_ + cc]),
                                   s01 * __ldcg(&h1src[m0 * H_ + cc + 1]), hi, lo);
                        *(uint32_t*)&d_arh[m0 * H_ + cc] = hi;
                        *(uint32_t*)&d_arl[m0 * H_ + cc] = lo;
                        split_pack(s10 * __ldcg(&h1src[m1r * H_ + cc]),
                                   s11 * __ldcg(&h1src[m1r * H_ + cc + 1]), hi, lo);
                        *(uint32_t*)&d_arh[m1r * H_ + cc] = hi;
                        *(uint32_t*)&d_arl[m1r * H_ + cc] = lo;
                    } else {
                        const int cc = col - 1536;
                        uint32_t hi, lo;
                        split_pack(s00 * __ldcg(&h0src[(size_t)m0 * lda0 + cc]),
                                   s01 * __ldcg(&h0src[(size_t)m0 * lda0 + cc + 1]),
                                   hi, lo);
                        *(uint32_t*)&d_aqh[m0 * H_ + cc] = hi;
                        *(uint32_t*)&d_aql[m0 * H_ + cc] = lo;
                        split_pack(s10 * __ldcg(&h0src[(size_t)m1r * lda0 + cc]),
                                   s11 * __ldcg(&h0src[(size_t)m1r * lda0 + cc + 1]),
                                   hi, lo);
                        *(uint32_t*)&d_aqh[m1r * H_ + cc] = hi;
                        *(uint32_t*)&d_aql[m1r * H_ + cc] = lo;
                    }
                }
                grid_barrier();

                // ---------- stage 2: candidate GEMM (32x32 tile, split-K) ----------
                {
                    const __nv_bfloat16* a0h = g0side ? h0sh : h1sh;
                    const __nv_bfloat16* a0l = g0side ? h0sl : h1sl;
                    const __nv_bfloat16* a1h = g0side ? d_arh : d_aqh;
                    const __nv_bfloat16* a1l = g0side ? d_arl : d_aql;
                    float acc[4];
                    gemm_s2(smb, smraw, m2base, n2base,
                            a0h, a0l, a1h, a1l,
                            d_gw_h + (size_t)cell * 1024 * 1024,
                            d_gw_l + (size_t)cell * 1024 * 1024, acc);

                    if (wid < 8) {
                        const int m0 = m2base + (wid & 1) * 16 + g, m1r = m0 + 8;
                        const int col = n2base + (wid >> 1) * 8 + tg * 2;
                        if (g0side) {
                            const float* bp = g0b + (size_t)cell * H_;
                            const float b0 = bp[col], b1 = bp[col + 1];
#pragma unroll
                            for (int rr = 0; rr < 2; ++rr) {
                                const int m = rr ? m1r : m0;
                                const float c0 = tanhf(acc[rr * 2 + 0] + b0);
                                const float c1 = tanhf(acc[rr * 2 + 1] + b1);
                                const float z0v = __ldcg(&d_z[m * 1024 + H_ + col]);
                                const float z1v = __ldcg(&d_z[m * 1024 + H_ + col + 1]);
                                const float o0 = __ldcg(&h1src[m * H_ + col]);
                                const float o1 = __ldcg(&h1src[m * H_ + col + 1]);
                                const float n0v = z0v * c0 + (1.f - z0v) * o0;
                                const float n1v = z1v * c1 + (1.f - z1v) * o1;
                                *(float2*)&h1dst[m * H_ + col] = make_float2(n0v, n1v);
                                uint32_t hi, lo;
                                split_pack(n0v, n1v, hi, lo);
                                *(uint32_t*)&h1dh[m * H_ + col] = hi;
                                *(uint32_t*)&h1dl[m * H_ + col] = lo;
                            }
                        } else {
                            const int n2 = col - 512;
                            const float* bp = g1b + (size_t)cell * H_;
                            const float b0 = bp[n2], b1 = bp[n2 + 1];
#pragma unroll
                            for (int rr = 0; rr < 2; ++rr) {
                                const int m = rr ? m1r : m0;
                                const float c0 = tanhf(acc[rr * 2 + 0] + b0);
                                const float c1 = tanhf(acc[rr * 2 + 1] + b1);
                                const float z0v = __ldcg(&d_z[m * 1024 + n2]);
                                const float z1v = __ldcg(&d_z[m * 1024 + n2 + 1]);
                                const float o0 = __ldcg(&h0src[(size_t)m * lda0 + n2]);
                                const float o1 =
                                    __ldcg(&h0src[(size_t)m * lda0 + n2 + 1]);
                                const float n0v = z0v * c0 + (1.f - z0v) * o0;
                                const float n1v = z1v * c1 + (1.f - z1v) * o1;
                                *(float2*)&h0dst[(size_t)m * ldh0d + n2] =
                                    make_float2(n0v, n1v);
                                if (!last) {
                                    uint32_t hi, lo;
                                    split_pack(n0v, n1v, hi, lo);
                                    *(uint32_t*)&h0dh[m * H_ + n2] = hi;
                                    *(uint32_t*)&h0dl[m * H_ + n2] = lo;
                                }
                            }
                        }
                    }
                    if (last && t + 1 < T_) {
                        for (int e = tid + blk * NTHR; e < B_ * H_; e += NBLK * NTHR) {
                            int b = e >> 9, h = e & (H_ - 1);
                            float v = __ldg(&H0in[((size_t)b * T_ + (t + 1)) * H_ + h]);
                            unsigned short hh, ll;
                            split2(v, hh, ll);
                            d_x0h[e] = *reinterpret_cast<__nv_bfloat16*>(&hh);
                            d_x0l[e] = *reinterpret_cast<__nv_bfloat16*>(&ll);
                        }
                    }
                }
                grid_barrier();
                p ^= 1;
            }
        }
    }

    for (int i = tid + blk * NTHR; i < L_ * B_ * H_; i += NBLK * NTHR) {
        int h    = i & (H_ - 1);
        int rest = i >> 9;
        int b    = rest & (B_ - 1);
        int l    = rest >> 7;
        out_h1[((size_t)b * L_ + l) * H_ + h] = __ldcg(&d_H1[i]);
    }
}

extern "C" void kernel_launch(void* const* d_in, const int* in_sizes, int n_in,
                              void* d_out, int out_size)
{
    const float* H0in  = (const float*)d_in[0];
    const float* lin_w = (const float*)d_in[1];
    const float* lin_b = (const float*)d_in[2];
    const float* g0w   = (const float*)d_in[3];
    const float* g0b   = (const float*)d_in[4];
    const float* g1w   = (const float*)d_in[5];
    const float* g1b   = (const float*)d_in[6];

    cudaFuncSetAttribute(lattice_mma,
                         cudaFuncAttributeMaxDynamicSharedMemorySize, SMEM_TOTAL);

    convert_weights<<<96, 256>>>(lin_w, g0w, g1w);
    lattice_mma<<<NBLK, NTHR, SMEM_TOTAL>>>(H0in, lin_b, g0b, g1b, (float*)d_out);
}